// round 8
// baseline (speedup 1.0000x reference)
#include <cuda_runtime.h>
#include <cuda_bf16.h>
#include <cstdint>

// DEQ via warp-level bf16 HMMA: z <- tanh(c + z B^T), 4 tanh applications,
// y = z4 . h + hb fused into the last GEMM iteration.
// R8: 384 threads (12 warps, 3/SMSP, ~170-reg cap) with fully independent
// per-warp 16-row bands: each warp computes its own c slice into private
// smem, __syncwarp only, no CTA barriers in the work loop. Persistent grid.

#define THREADS 384
#define NWARPS  12
#define LDB_B   272        // bytes per B row (136 bf16: conflict-free LDSM)
#define LDC_F   132        // floats per c row
#define CSLICE  (16 * LDC_F * 4)   // 8448 B per warp
#define SM_B    0                  // 34816 B
#define SM_C    34816              // 12 * 8448 = 101376 B
#define SM_H    136192             // 512 B
#define SM_AW   136704             // 2048 B
#define SM_AB   138752             // 512 B
#define SM_TOTAL 139264

__device__ __forceinline__ float tanh_exact(float v) {
    float e = __expf(2.0f * v);
    return 1.0f - __fdividef(2.0f, e + 1.0f);
}
__device__ __forceinline__ float tanh_apx(float v) {
    float r; asm("tanh.approx.f32 %0, %1;" : "=f"(r) : "f"(v)); return r;
}
__device__ __forceinline__ uint32_t packlh(float lo, float hi) {
    uint32_t r;
    asm("cvt.rn.satfinite.bf16x2.f32 %0, %1, %2;" : "=r"(r) : "f"(hi), "f"(lo));
    return r;
}
__device__ __forceinline__ void mma16816(float* d, const uint32_t* a,
                                         uint32_t b0, uint32_t b1) {
    asm volatile(
        "mma.sync.aligned.m16n8k16.row.col.f32.bf16.bf16.f32 "
        "{%0,%1,%2,%3}, {%4,%5,%6,%7}, {%8,%9}, {%0,%1,%2,%3};"
        : "+f"(d[0]), "+f"(d[1]), "+f"(d[2]), "+f"(d[3])
        : "r"(a[0]), "r"(a[1]), "r"(a[2]), "r"(a[3]), "r"(b0), "r"(b1));
}
__device__ __forceinline__ void ldsm4(uint32_t* r, uint32_t addr) {
    asm volatile("ldmatrix.sync.aligned.m8n8.x4.shared.b16 {%0,%1,%2,%3}, [%4];"
                 : "=r"(r[0]), "=r"(r[1]), "=r"(r[2]), "=r"(r[3]) : "r"(addr));
}

// One GEMM iteration: out = z_cur * B^T; z_next = tanh(c + out) (or y-reduce on LAST)
template<bool LAST>
__device__ __forceinline__ void gemm_iter(
    uint32_t bb, const float2* c2w, const float2* c2w8, const float2* h2,
    const uint32_t A[8][4], uint32_t An[8][4],
    float& y0, float& y1, int qc)
{
    #pragma unroll
    for (int ntp = 0; ntp < 8; ++ntp) {
        const uint32_t b0a = bb + (uint32_t)(2 * ntp)     * (8 * LDB_B);
        const uint32_t b1a = bb + (uint32_t)(2 * ntp + 1) * (8 * LDB_B);
        float acc0[4] = {0.f, 0.f, 0.f, 0.f};
        float acc1[4] = {0.f, 0.f, 0.f, 0.f};
        #pragma unroll
        for (int l = 0; l < 4; ++l) {
            uint32_t b0[4], b1[4];
            ldsm4(b0, b0a + l * 64);
            ldsm4(b1, b1a + l * 64);
            mma16816(acc0, A[2 * l],     b0[0], b0[1]);
            mma16816(acc0, A[2 * l + 1], b0[2], b0[3]);
            mma16816(acc1, A[2 * l],     b1[0], b1[1]);
            mma16816(acc1, A[2 * l + 1], b1[2], b1[3]);
        }
        #pragma unroll
        for (int h = 0; h < 2; ++h) {
            const int nt = 2 * ntp + h;
            const float* acc = h ? acc1 : acc0;
            float2 cl0 = c2w [4 * nt + qc];
            float2 cl1 = c2w8[4 * nt + qc];
            float p0 = acc[0] + cl0.x, p1 = acc[1] + cl0.y;
            float p2 = acc[2] + cl1.x, p3 = acc[3] + cl1.y;
            if (LAST) {
                float2 hv = h2[4 * nt + qc];
                y0 += hv.x * tanh_exact(p0) + hv.y * tanh_exact(p1);
                y1 += hv.x * tanh_exact(p2) + hv.y * tanh_exact(p3);
            } else {
                An[ntp][2 * h + 0] = packlh(tanh_apx(p0), tanh_apx(p1));
                An[ntp][2 * h + 1] = packlh(tanh_apx(p2), tanh_apx(p3));
            }
        }
    }
}

__global__ void __launch_bounds__(THREADS, 1)
deq_mma_kernel(const float* __restrict__ x,
               const float* __restrict__ Aw,
               const float* __restrict__ Ab,
               const float* __restrict__ Bw,
               const float* __restrict__ Bb,
               const float* __restrict__ hw,
               const float* __restrict__ hb,
               float* __restrict__ out,
               int nbands)
{
    extern __shared__ char smem[];
    const int tid = threadIdx.x;

    // ---- one-time staging: B (bf16, padded rows), h, Aw, Ab+Bb ----
    for (int idx = tid; idx < 128 * 128; idx += THREADS) {
        int i = idx >> 7, j = idx & 127;
        *(__nv_bfloat16*)(smem + SM_B + i * LDB_B + j * 2) = __float2bfloat16(Bw[idx]);
    }
    if (tid < 128) {
        ((float*)(smem + SM_H))[tid]  = hw[tid];
        ((float*)(smem + SM_AB))[tid] = Ab[tid] + Bb[tid];
        ((float4*)(smem + SM_AW))[tid] = ((const float4*)Aw)[tid];
    }
    __syncthreads();

    // ---- per-thread constants ----
    const int lane = tid & 31, wid = tid >> 5;
    const int qr = lane >> 2, qc = lane & 3;
    float* cbase = (float*)(smem + SM_C + wid * CSLICE);   // this warp's c slice
    const float2* c2w  = (const float2*)cbase + qr * (LDC_F / 2);
    const float2* c2w8 = c2w + 8 * (LDC_F / 2);
    const float2* h2   = (const float2*)(smem + SM_H);
    const float*  abv  = (const float*)(smem + SM_AB);
    const float4* awv  = (const float4*)(smem + SM_AW);
    const uint32_t sb  = (uint32_t)__cvta_generic_to_shared(smem);
    const uint32_t bb  = sb + SM_B + (uint32_t)(lane & 7) * LDB_B + (uint32_t)(lane >> 3) * 16;
    const float hb0 = hb[0];

    const int cr  = lane >> 1;          // c-compute: this lane's row in band
    const int ci0 = (lane & 1) << 6;    // and its half of the state dim
    float* crow = cbase + cr * LDC_F;

    for (int band = blockIdx.x * NWARPS + wid; band < nbands;
         band += gridDim.x * NWARPS) {
        const int row0 = band * 16;

        // ---- c = x A^T + (A_b + B_b) for this band (warp-private) ----
        __syncwarp();   // previous band's c reads are done
        {
            float4 xv = ((const float4*)x)[row0 + cr];
            #pragma unroll 8
            for (int k = 0; k < 64; ++k) {
                int i = ci0 + k;
                float4 a = awv[i];
                crow[i] = abv[i] + xv.x * a.x + xv.y * a.y + xv.z * a.z + xv.w * a.w;
            }
        }
        __syncwarp();

        // ---- z1 = tanh(c) into A fragments ----
        uint32_t A[8][4], An[8][4];
        #pragma unroll
        for (int kt = 0; kt < 8; ++kt) {
            float2 u0 = c2w [8 * kt + qc];
            float2 u1 = c2w8[8 * kt + qc];
            float2 u2 = c2w [8 * kt + 4 + qc];
            float2 u3 = c2w8[8 * kt + 4 + qc];
            A[kt][0] = packlh(tanh_apx(u0.x), tanh_apx(u0.y));
            A[kt][1] = packlh(tanh_apx(u1.x), tanh_apx(u1.y));
            A[kt][2] = packlh(tanh_apx(u2.x), tanh_apx(u2.y));
            A[kt][3] = packlh(tanh_apx(u3.x), tanh_apx(u3.y));
        }

        // ---- 3 GEMM iterations (z2, z3, z4); last fuses y = z4 . h ----
        float y0 = 0.f, y1 = 0.f;
        gemm_iter<false>(bb, c2w, c2w8, h2, A,  An, y0, y1, qc);
        gemm_iter<false>(bb, c2w, c2w8, h2, An, A,  y0, y1, qc);
        gemm_iter<true >(bb, c2w, c2w8, h2, A,  An, y0, y1, qc);

        // ---- reduce y across the 4 lanes sharing a row, write out ----
        y0 += __shfl_xor_sync(0xffffffffu, y0, 1);
        y0 += __shfl_xor_sync(0xffffffffu, y0, 2);
        y1 += __shfl_xor_sync(0xffffffffu, y1, 1);
        y1 += __shfl_xor_sync(0xffffffffu, y1, 2);
        if (qc == 0) {
            out[row0 + qr]     = y0 + hb0;
            out[row0 + qr + 8] = y1 + hb0;
        }
    }
}

extern "C" void kernel_launch(void* const* d_in, const int* in_sizes, int n_in,
                              void* d_out, int out_size) {
    const float* x  = (const float*)d_in[0];
    const float* Aw = (const float*)d_in[1];
    const float* Ab = (const float*)d_in[2];
    const float* Bw = (const float*)d_in[3];
    const float* Bb = (const float*)d_in[4];
    const float* hw = (const float*)d_in[5];
    const float* hb = (const float*)d_in[6];
    float* out = (float*)d_out;

    int batch  = in_sizes[0] / 4;   // x is [batch, 4]
    int nbands = batch / 16;        // 8192
    int grid   = 148;               // persistent: one CTA per SM

    cudaFuncSetAttribute(deq_mma_kernel,
                         cudaFuncAttributeMaxDynamicSharedMemorySize,
                         SM_TOTAL);
    deq_mma_kernel<<<grid, THREADS, SM_TOTAL>>>(x, Aw, Ab, Bw, Bb, hw, hb, out, nbands);
}

// round 9
// speedup vs baseline: 1.0457x; 1.0457x over previous
#include <cuda_runtime.h>
#include <cuda_bf16.h>
#include <cstdint>

// DEQ via warp-level bf16 HMMA: z <- tanh(c + z B^T), 4 tanh applications,
// y = z4 . h + hb fused into the last GEMM iteration.
// R9: back to 256 threads / 255-reg budget (R8 showed 168-reg cap spills),
// but each warp now owns TWO 16-row bands (CTA tile = 256 rows): 4 independent
// HMMA chains per B-fragment load -> 2x in-warp ILP on a latency-bound kernel,
// and half the LDSM traffic per MAC. Persistent grid, CTA-level c compute.

#define THREADS 256
#define LDB_B   272        // bytes per B row (136 bf16: conflict-free LDSM)
#define LDC_F   132        // floats per c row
#define SM_B    0          // 34816 B
#define SM_C    34816      // 256 * 528 = 135168 B
#define SM_H    169984     // 512 B
#define SM_AW   170496     // 2048 B
#define SM_AB   172544     // 512 B
#define SM_TOTAL 173056

__device__ __forceinline__ float tanh_exact(float v) {
    float e = __expf(2.0f * v);
    return 1.0f - __fdividef(2.0f, e + 1.0f);
}
__device__ __forceinline__ float tanh_apx(float v) {
    float r; asm("tanh.approx.f32 %0, %1;" : "=f"(r) : "f"(v)); return r;
}
__device__ __forceinline__ uint32_t packlh(float lo, float hi) {
    uint32_t r;
    asm("cvt.rn.satfinite.bf16x2.f32 %0, %1, %2;" : "=r"(r) : "f"(hi), "f"(lo));
    return r;
}
__device__ __forceinline__ void mma16816(float* d, const uint32_t* a,
                                         uint32_t b0, uint32_t b1) {
    asm volatile(
        "mma.sync.aligned.m16n8k16.row.col.f32.bf16.bf16.f32 "
        "{%0,%1,%2,%3}, {%4,%5,%6,%7}, {%8,%9}, {%0,%1,%2,%3};"
        : "+f"(d[0]), "+f"(d[1]), "+f"(d[2]), "+f"(d[3])
        : "r"(a[0]), "r"(a[1]), "r"(a[2]), "r"(a[3]), "r"(b0), "r"(b1));
}
__device__ __forceinline__ void ldsm4(uint32_t* r, uint32_t addr) {
    asm volatile("ldmatrix.sync.aligned.m8n8.x4.shared.b16 {%0,%1,%2,%3}, [%4];"
                 : "=r"(r[0]), "=r"(r[1]), "=r"(r[2]), "=r"(r[3]) : "r"(addr));
}

// One GEMM iteration over TWO bands: out = z * B^T; z_next = tanh(c + out)
// (or y-reduce on LAST). A0/An0 = band 0 (rows rb..rb+15), A1/An1 = band 1
// (rows rb+16..rb+31). B fragments are shared by all four accumulator chains.
template<bool LAST>
__device__ __forceinline__ void gemm_iter2(
    uint32_t bb,
    const float2* c0a, const float2* c0b,   // band0: rows rb+qr, rb+qr+8
    const float2* c1a, const float2* c1b,   // band1: rows rb+16+qr, rb+24+qr
    const float2* h2,
    const uint32_t A0[8][4], const uint32_t A1[8][4],
    uint32_t An0[8][4], uint32_t An1[8][4],
    float* y, int qc)
{
    #pragma unroll
    for (int ntp = 0; ntp < 8; ++ntp) {
        const uint32_t b0a = bb + (uint32_t)(2 * ntp)     * (8 * LDB_B);
        const uint32_t b1a = bb + (uint32_t)(2 * ntp + 1) * (8 * LDB_B);
        float a00[4] = {0.f,0.f,0.f,0.f};   // band0, even n-tile
        float a01[4] = {0.f,0.f,0.f,0.f};   // band0, odd  n-tile
        float a10[4] = {0.f,0.f,0.f,0.f};   // band1, even n-tile
        float a11[4] = {0.f,0.f,0.f,0.f};   // band1, odd  n-tile
        #pragma unroll
        for (int l = 0; l < 4; ++l) {
            uint32_t b0[4], b1[4];
            ldsm4(b0, b0a + l * 64);
            ldsm4(b1, b1a + l * 64);
            mma16816(a00, A0[2*l],   b0[0], b0[1]);
            mma16816(a10, A1[2*l],   b0[0], b0[1]);
            mma16816(a01, A0[2*l],   b1[0], b1[1]);
            mma16816(a11, A1[2*l],   b1[0], b1[1]);
            mma16816(a00, A0[2*l+1], b0[2], b0[3]);
            mma16816(a10, A1[2*l+1], b0[2], b0[3]);
            mma16816(a01, A0[2*l+1], b1[2], b1[3]);
            mma16816(a11, A1[2*l+1], b1[2], b1[3]);
        }
        #pragma unroll
        for (int h = 0; h < 2; ++h) {
            const int nt = 2 * ntp + h;
            const float* ac0 = h ? a01 : a00;
            const float* ac1 = h ? a11 : a10;
            float2 u0 = c0a[4 * nt + qc];
            float2 u1 = c0b[4 * nt + qc];
            float2 u2 = c1a[4 * nt + qc];
            float2 u3 = c1b[4 * nt + qc];
            float p0 = ac0[0] + u0.x, p1 = ac0[1] + u0.y;
            float p2 = ac0[2] + u1.x, p3 = ac0[3] + u1.y;
            float p4 = ac1[0] + u2.x, p5 = ac1[1] + u2.y;
            float p6 = ac1[2] + u3.x, p7 = ac1[3] + u3.y;
            if (LAST) {
                float2 hv = h2[4 * nt + qc];
                y[0] += hv.x * tanh_exact(p0) + hv.y * tanh_exact(p1);
                y[1] += hv.x * tanh_exact(p2) + hv.y * tanh_exact(p3);
                y[2] += hv.x * tanh_exact(p4) + hv.y * tanh_exact(p5);
                y[3] += hv.x * tanh_exact(p6) + hv.y * tanh_exact(p7);
            } else {
                An0[ntp][2*h]   = packlh(tanh_apx(p0), tanh_apx(p1));
                An0[ntp][2*h+1] = packlh(tanh_apx(p2), tanh_apx(p3));
                An1[ntp][2*h]   = packlh(tanh_apx(p4), tanh_apx(p5));
                An1[ntp][2*h+1] = packlh(tanh_apx(p6), tanh_apx(p7));
            }
        }
    }
}

__global__ void __launch_bounds__(THREADS, 1)
deq_mma_kernel(const float* __restrict__ x,
               const float* __restrict__ Aw,
               const float* __restrict__ Ab,
               const float* __restrict__ Bw,
               const float* __restrict__ Bb,
               const float* __restrict__ hw,
               const float* __restrict__ hb,
               float* __restrict__ out,
               int ntiles)
{
    extern __shared__ char smem[];
    const int tid = threadIdx.x;

    // ---- one-time staging: B (bf16, padded rows), h, Aw, Ab+Bb ----
    #pragma unroll 4
    for (int idx = tid; idx < 128 * 128; idx += THREADS) {
        int i = idx >> 7, j = idx & 127;
        *(__nv_bfloat16*)(smem + SM_B + i * LDB_B + j * 2) = __float2bfloat16(Bw[idx]);
    }
    if (tid < 128) {
        ((float*)(smem + SM_H))[tid]  = hw[tid];
        ((float*)(smem + SM_AB))[tid] = Ab[tid] + Bb[tid];
        ((float4*)(smem + SM_AW))[tid] = ((const float4*)Aw)[tid];
    }

    // ---- per-thread constants ----
    const int lane = tid & 31, wid = tid >> 5;
    const int qr = lane >> 2, qc = lane & 3;
    const int rb = wid * 32;                  // this warp's 32-row block
    const float2* c2 = (const float2*)(smem + SM_C);
    const float2* c0a = c2 + (rb + qr)      * (LDC_F / 2);
    const float2* c0b = c2 + (rb + qr + 8)  * (LDC_F / 2);
    const float2* c1a = c2 + (rb + qr + 16) * (LDC_F / 2);
    const float2* c1b = c2 + (rb + qr + 24) * (LDC_F / 2);
    const float2* h2  = (const float2*)(smem + SM_H);
    const float*  abv = (const float*)(smem + SM_AB);
    const float4* awv = (const float4*)(smem + SM_AW);
    const uint32_t sb = (uint32_t)__cvta_generic_to_shared(smem);
    const uint32_t bb = sb + SM_B + (uint32_t)(lane & 7) * LDB_B + (uint32_t)(lane >> 3) * 16;
    const float hb0 = hb[0];

    float* crow = (float*)(smem + SM_C) + tid * LDC_F;   // c compute: thread = row

    for (int tile = blockIdx.x; tile < ntiles; tile += gridDim.x) {
        const int row0 = tile * 256;

        // ---- c = x A^T + (A_b + B_b), 256 rows, thread = row ----
        __syncthreads();   // previous tile's c reads are done
        {
            float4 xv = ((const float4*)x)[row0 + tid];
            #pragma unroll 8
            for (int i = 0; i < 128; ++i) {
                float4 a = awv[i];
                crow[i] = abv[i] + xv.x * a.x + xv.y * a.y + xv.z * a.z + xv.w * a.w;
            }
        }
        __syncthreads();

        // ---- z1 = tanh(c) into A fragments (both bands) ----
        uint32_t A0[8][4], A1[8][4], An0[8][4], An1[8][4];
        #pragma unroll
        for (int kt = 0; kt < 8; ++kt) {
            float2 u0 = c0a[8 * kt + qc],     u1 = c0b[8 * kt + qc];
            float2 u2 = c0a[8 * kt + 4 + qc], u3 = c0b[8 * kt + 4 + qc];
            float2 v0 = c1a[8 * kt + qc],     v1 = c1b[8 * kt + qc];
            float2 v2 = c1a[8 * kt + 4 + qc], v3 = c1b[8 * kt + 4 + qc];
            A0[kt][0] = packlh(tanh_apx(u0.x), tanh_apx(u0.y));
            A0[kt][1] = packlh(tanh_apx(u1.x), tanh_apx(u1.y));
            A0[kt][2] = packlh(tanh_apx(u2.x), tanh_apx(u2.y));
            A0[kt][3] = packlh(tanh_apx(u3.x), tanh_apx(u3.y));
            A1[kt][0] = packlh(tanh_apx(v0.x), tanh_apx(v0.y));
            A1[kt][1] = packlh(tanh_apx(v1.x), tanh_apx(v1.y));
            A1[kt][2] = packlh(tanh_apx(v2.x), tanh_apx(v2.y));
            A1[kt][3] = packlh(tanh_apx(v3.x), tanh_apx(v3.y));
        }

        // ---- 3 GEMM iterations (z2, z3, z4); last fuses y = z4 . h ----
        float y[4] = {0.f, 0.f, 0.f, 0.f};
        gemm_iter2<false>(bb, c0a, c0b, c1a, c1b, h2, A0,  A1,  An0, An1, y, qc);
        gemm_iter2<false>(bb, c0a, c0b, c1a, c1b, h2, An0, An1, A0,  A1,  y, qc);
        gemm_iter2<true >(bb, c0a, c0b, c1a, c1b, h2, A0,  A1,  An0, An1, y, qc);

        // ---- reduce y across the 4 lanes sharing a row, write out ----
        #pragma unroll
        for (int k = 0; k < 4; ++k) {
            y[k] += __shfl_xor_sync(0xffffffffu, y[k], 1);
            y[k] += __shfl_xor_sync(0xffffffffu, y[k], 2);
        }
        if (qc == 0) {
            out[row0 + rb + qr]      = y[0] + hb0;
            out[row0 + rb + qr + 8]  = y[1] + hb0;
            out[row0 + rb + qr + 16] = y[2] + hb0;
            out[row0 + rb + qr + 24] = y[3] + hb0;
        }
    }
}

extern "C" void kernel_launch(void* const* d_in, const int* in_sizes, int n_in,
                              void* d_out, int out_size) {
    const float* x  = (const float*)d_in[0];
    const float* Aw = (const float*)d_in[1];
    const float* Ab = (const float*)d_in[2];
    const float* Bw = (const float*)d_in[3];
    const float* Bb = (const float*)d_in[4];
    const float* hw = (const float*)d_in[5];
    const float* hb = (const float*)d_in[6];
    float* out = (float*)d_out;

    int batch  = in_sizes[0] / 4;   // x is [batch, 4]
    int ntiles = batch / 256;       // 512
    int grid   = 148;               // persistent: one CTA per SM

    cudaFuncSetAttribute(deq_mma_kernel,
                         cudaFuncAttributeMaxDynamicSharedMemorySize,
                         SM_TOTAL);
    deq_mma_kernel<<<grid, THREADS, SM_TOTAL>>>(x, Aw, Ab, Bw, Bb, hw, hb, out, ntiles);
}

// round 10
// speedup vs baseline: 1.1961x; 1.1439x over previous
#include <cuda_runtime.h>
#include <cuda_bf16.h>
#include <cstdint>

// DEQ via warp-level bf16 HMMA: z <- tanh(c + z B^T), 4 tanh applications,
// y = z4 . h + hb fused into the last GEMM iteration.
// R10 = R7 (256 thr / 255 regs / 1 band per warp / persistent grid) with
// split accumulators: each of acc0/acc1 becomes two partial sums (even/odd
// k-step), giving 4 independent HMMA chains of depth 4 instead of 2 chains
// of depth 8 — attacks the chain-latency bound seen at tensor=19%/issue=20%.

#define THREADS 256
#define LDB_B   272        // bytes per B row (136 bf16: conflict-free LDSM)
#define LDC_F   132        // floats per c row
#define SM_B    0          // 34816 B
#define SM_C    34816      // 67584 B
#define SM_H    102400     // 512 B
#define SM_AW   102912     // 2048 B
#define SM_AB   104960     // 512 B
#define SM_TOTAL 105472

__device__ __forceinline__ float tanh_exact(float v) {
    float e = __expf(2.0f * v);
    return 1.0f - __fdividef(2.0f, e + 1.0f);
}
__device__ __forceinline__ float tanh_apx(float v) {
    float r; asm("tanh.approx.f32 %0, %1;" : "=f"(r) : "f"(v)); return r;
}
__device__ __forceinline__ uint32_t packlh(float lo, float hi) {
    uint32_t r;
    asm("cvt.rn.satfinite.bf16x2.f32 %0, %1, %2;" : "=r"(r) : "f"(hi), "f"(lo));
    return r;
}
__device__ __forceinline__ void mma16816(float* d, const uint32_t* a,
                                         uint32_t b0, uint32_t b1) {
    asm volatile(
        "mma.sync.aligned.m16n8k16.row.col.f32.bf16.bf16.f32 "
        "{%0,%1,%2,%3}, {%4,%5,%6,%7}, {%8,%9}, {%0,%1,%2,%3};"
        : "+f"(d[0]), "+f"(d[1]), "+f"(d[2]), "+f"(d[3])
        : "r"(a[0]), "r"(a[1]), "r"(a[2]), "r"(a[3]), "r"(b0), "r"(b1));
}
__device__ __forceinline__ void ldsm4(uint32_t* r, uint32_t addr) {
    asm volatile("ldmatrix.sync.aligned.m8n8.x4.shared.b16 {%0,%1,%2,%3}, [%4];"
                 : "=r"(r[0]), "=r"(r[1]), "=r"(r[2]), "=r"(r[3]) : "r"(addr));
}

// One GEMM iteration: out = z_cur * B^T; z_next = tanh(c + out) (or y-reduce on LAST)
template<bool LAST>
__device__ __forceinline__ void gemm_iter(
    uint32_t bb, const float2* c2w, const float2* c2w8, const float2* h2,
    const uint32_t A[8][4], uint32_t An[8][4],
    float& y0, float& y1, int qc)
{
    #pragma unroll
    for (int ntp = 0; ntp < 8; ++ntp) {
        const uint32_t b0a = bb + (uint32_t)(2 * ntp)     * (8 * LDB_B);
        const uint32_t b1a = bb + (uint32_t)(2 * ntp + 1) * (8 * LDB_B);
        // 4 independent chains: {acc0,acc1} x {even l, odd l}, depth 4 each
        float a0e[4] = {0.f,0.f,0.f,0.f}, a0o[4] = {0.f,0.f,0.f,0.f};
        float a1e[4] = {0.f,0.f,0.f,0.f}, a1o[4] = {0.f,0.f,0.f,0.f};
        #pragma unroll
        for (int l = 0; l < 4; ++l) {
            uint32_t b0[4], b1[4];
            ldsm4(b0, b0a + l * 64);
            ldsm4(b1, b1a + l * 64);
            float* d0 = (l & 1) ? a0o : a0e;
            float* d1 = (l & 1) ? a1o : a1e;
            mma16816(d0, A[2 * l],     b0[0], b0[1]);
            mma16816(d1, A[2 * l],     b1[0], b1[1]);
            mma16816(d0, A[2 * l + 1], b0[2], b0[3]);
            mma16816(d1, A[2 * l + 1], b1[2], b1[3]);
        }
        float acc0[4], acc1[4];
        #pragma unroll
        for (int k = 0; k < 4; ++k) {
            acc0[k] = a0e[k] + a0o[k];
            acc1[k] = a1e[k] + a1o[k];
        }
        #pragma unroll
        for (int h = 0; h < 2; ++h) {
            const int nt = 2 * ntp + h;
            const float* acc = h ? acc1 : acc0;
            float2 cl0 = c2w [4 * nt + qc];
            float2 cl1 = c2w8[4 * nt + qc];
            float p0 = acc[0] + cl0.x, p1 = acc[1] + cl0.y;
            float p2 = acc[2] + cl1.x, p3 = acc[3] + cl1.y;
            if (LAST) {
                float2 hv = h2[4 * nt + qc];
                y0 += hv.x * tanh_exact(p0) + hv.y * tanh_exact(p1);
                y1 += hv.x * tanh_exact(p2) + hv.y * tanh_exact(p3);
            } else {
                An[ntp][2 * h + 0] = packlh(tanh_apx(p0), tanh_apx(p1));
                An[ntp][2 * h + 1] = packlh(tanh_apx(p2), tanh_apx(p3));
            }
        }
    }
}

__global__ void __launch_bounds__(THREADS, 1)
deq_mma_kernel(const float* __restrict__ x,
               const float* __restrict__ Aw,
               const float* __restrict__ Ab,
               const float* __restrict__ Bw,
               const float* __restrict__ Bb,
               const float* __restrict__ hw,
               const float* __restrict__ hb,
               float* __restrict__ out,
               int ntiles)
{
    extern __shared__ char smem[];
    const int tid = threadIdx.x;

    // ---- one-time staging: B (bf16, padded rows), h, Aw, Ab+Bb ----
    #pragma unroll 4
    for (int idx = tid; idx < 128 * 128; idx += THREADS) {
        int i = idx >> 7, j = idx & 127;
        *(__nv_bfloat16*)(smem + SM_B + i * LDB_B + j * 2) = __float2bfloat16(Bw[idx]);
    }
    if (tid < 128) {
        ((float*)(smem + SM_H))[tid]  = hw[tid];
        ((float*)(smem + SM_AB))[tid] = Ab[tid] + Bb[tid];
        ((float4*)(smem + SM_AW))[tid] = ((const float4*)Aw)[tid];
    }

    // ---- per-thread constants ----
    const int lane = tid & 31, wid = tid >> 5;
    const int qr = lane >> 2, qc = lane & 3;
    const int rb = wid * 16;
    const float2* c2   = (const float2*)(smem + SM_C);
    const float2* c2w  = c2 + (rb + qr) * (LDC_F / 2);
    const float2* c2w8 = c2w + 8 * (LDC_F / 2);
    const float2* h2   = (const float2*)(smem + SM_H);
    const float*  abv  = (const float*)(smem + SM_AB);
    const float4* awv  = (const float4*)(smem + SM_AW);
    const uint32_t sb  = (uint32_t)__cvta_generic_to_shared(smem);
    const uint32_t bb  = sb + SM_B + (uint32_t)(lane & 7) * LDB_B + (uint32_t)(lane >> 3) * 16;
    const float hb0 = hb[0];

    const int cr  = tid >> 1;
    const int ci0 = (tid & 1) << 6;
    float* crow = (float*)(smem + SM_C) + cr * LDC_F;

    for (int tile = blockIdx.x; tile < ntiles; tile += gridDim.x) {
        const int row0 = tile * 128;

        // ---- c = x A^T + (A_b + B_b) for this tile ----
        __syncthreads();   // previous tile's GEMM reads of c are done
        {
            float4 xv = ((const float4*)x)[row0 + cr];
            #pragma unroll 8
            for (int k = 0; k < 64; ++k) {
                int i = ci0 + k;
                float4 a = awv[i];
                crow[i] = abv[i] + xv.x * a.x + xv.y * a.y + xv.z * a.z + xv.w * a.w;
            }
        }
        __syncthreads();

        // ---- z1 = tanh(c) into A fragments ----
        uint32_t A[8][4], An[8][4];
        #pragma unroll
        for (int kt = 0; kt < 8; ++kt) {
            float2 u0 = c2w [8 * kt + qc];
            float2 u1 = c2w8[8 * kt + qc];
            float2 u2 = c2w [8 * kt + 4 + qc];
            float2 u3 = c2w8[8 * kt + 4 + qc];
            A[kt][0] = packlh(tanh_apx(u0.x), tanh_apx(u0.y));
            A[kt][1] = packlh(tanh_apx(u1.x), tanh_apx(u1.y));
            A[kt][2] = packlh(tanh_apx(u2.x), tanh_apx(u2.y));
            A[kt][3] = packlh(tanh_apx(u3.x), tanh_apx(u3.y));
        }

        // ---- 3 GEMM iterations (z2, z3, z4); last fuses y = z4 . h ----
        float y0 = 0.f, y1 = 0.f;
        gemm_iter<false>(bb, c2w, c2w8, h2, A,  An, y0, y1, qc);
        gemm_iter<false>(bb, c2w, c2w8, h2, An, A,  y0, y1, qc);
        gemm_iter<true >(bb, c2w, c2w8, h2, A,  An, y0, y1, qc);

        // ---- reduce y across the 4 lanes sharing a row, write out ----
        y0 += __shfl_xor_sync(0xffffffffu, y0, 1);
        y0 += __shfl_xor_sync(0xffffffffu, y0, 2);
        y1 += __shfl_xor_sync(0xffffffffu, y1, 1);
        y1 += __shfl_xor_sync(0xffffffffu, y1, 2);
        if (qc == 0) {
            out[row0 + rb + qr]     = y0 + hb0;
            out[row0 + rb + qr + 8] = y1 + hb0;
        }
    }
}

extern "C" void kernel_launch(void* const* d_in, const int* in_sizes, int n_in,
                              void* d_out, int out_size) {
    const float* x  = (const float*)d_in[0];
    const float* Aw = (const float*)d_in[1];
    const float* Ab = (const float*)d_in[2];
    const float* Bw = (const float*)d_in[3];
    const float* Bb = (const float*)d_in[4];
    const float* hw = (const float*)d_in[5];
    const float* hb = (const float*)d_in[6];
    float* out = (float*)d_out;

    int batch  = in_sizes[0] / 4;   // x is [batch, 4]
    int ntiles = batch / 128;       // 1024
    int grid   = 148;               // persistent: one CTA per SM

    cudaFuncSetAttribute(deq_mma_kernel,
                         cudaFuncAttributeMaxDynamicSharedMemorySize,
                         SM_TOTAL);
    deq_mma_kernel<<<grid, THREADS, SM_TOTAL>>>(x, Aw, Ab, Bw, Bb, hw, hb, out, ntiles);
}

// round 11
// speedup vs baseline: 1.9019x; 1.5901x over previous
#include <cuda_runtime.h>
#include <cuda_bf16.h>
#include <cstdint>

// DEQ via warp-level bf16 HMMA: z <- tanh(c + z B^T), 4 tanh applications,
// y = z4 . h + hb fused into the last GEMM iteration.
// R11: z lives in per-warp SMEM (bf16, ldmatrix layout) between iterations
// instead of in 64 registers (A+An). Live set ~80 regs -> 384 threads
// (3 warps/SMSP) WITHOUT the R8 spills. Fully independent per-warp 16-row
// bands, __syncwarp only, persistent grid.

#define THREADS 384
#define NWARPS  12
#define LDB_B   272        // bytes per B row (136 bf16: conflict-free LDSM)
#define LDZ_B   272        // bytes per z row (same padding)
#define LDC_F   132        // floats per c row
#define ZSLICE  (16 * LDZ_B)        // 4352 B per warp
#define CSLICE  (16 * LDC_F * 4)    // 8448 B per warp
#define SM_B    0                   // 34816 B
#define SM_Z    34816               // 12 * 4352 = 52224 B
#define SM_C    87040               // 12 * 8448 = 101376 B
#define SM_H    188416              // 512 B
#define SM_AW   188928              // 2048 B
#define SM_AB   190976              // 512 B
#define SM_TOTAL 191488

__device__ __forceinline__ float tanh_exact(float v) {
    float e = __expf(2.0f * v);
    return 1.0f - __fdividef(2.0f, e + 1.0f);
}
__device__ __forceinline__ float tanh_apx(float v) {
    float r; asm("tanh.approx.f32 %0, %1;" : "=f"(r) : "f"(v)); return r;
}
// pack {lo, hi} floats into bf16x2 (lo -> low 16 bits)
__device__ __forceinline__ uint32_t packlh(float lo, float hi) {
    uint32_t r;
    asm("cvt.rn.satfinite.bf16x2.f32 %0, %1, %2;" : "=r"(r) : "f"(hi), "f"(lo));
    return r;
}
__device__ __forceinline__ void mma16816(float* d, const uint32_t* a,
                                         uint32_t b0, uint32_t b1) {
    asm volatile(
        "mma.sync.aligned.m16n8k16.row.col.f32.bf16.bf16.f32 "
        "{%0,%1,%2,%3}, {%4,%5,%6,%7}, {%8,%9}, {%0,%1,%2,%3};"
        : "+f"(d[0]), "+f"(d[1]), "+f"(d[2]), "+f"(d[3])
        : "r"(a[0]), "r"(a[1]), "r"(a[2]), "r"(a[3]), "r"(b0), "r"(b1));
}
__device__ __forceinline__ void ldsm4(uint32_t* r, uint32_t addr) {
    asm volatile("ldmatrix.sync.aligned.m8n8.x4.shared.b16 {%0,%1,%2,%3}, [%4];"
                 : "=r"(r[0]), "=r"(r[1]), "=r"(r[2]), "=r"(r[3]) : "r"(addr));
}
__device__ __forceinline__ void sts32(uint32_t addr, uint32_t v) {
    asm volatile("st.shared.b32 [%0], %1;" :: "r"(addr), "r"(v) : "memory");
}

// One GEMM iteration: out = z_cur * B^T (A fragments loaded from Z smem);
// z_next = tanh(c + out) -> STS back to Z smem (or y-reduce on LAST).
template<bool LAST>
__device__ __forceinline__ void gemm_iter(
    uint32_t bb, uint32_t za, uint32_t zs,
    const float2* c2w, const float2* c2w8, const float2* h2,
    float& y0, float& y1, int qc)
{
    // load A fragments for this iteration (z_cur)
    uint32_t A[8][4];
    #pragma unroll
    for (int kt = 0; kt < 8; ++kt)
        ldsm4(A[kt], za + kt * 32);

    #pragma unroll
    for (int ntp = 0; ntp < 8; ++ntp) {
        const uint32_t b0a = bb + (uint32_t)(2 * ntp)     * (8 * LDB_B);
        const uint32_t b1a = bb + (uint32_t)(2 * ntp + 1) * (8 * LDB_B);
        float acc0[4] = {0.f, 0.f, 0.f, 0.f};
        float acc1[4] = {0.f, 0.f, 0.f, 0.f};
        #pragma unroll
        for (int l = 0; l < 4; ++l) {
            uint32_t b0[4], b1[4];
            ldsm4(b0, b0a + l * 64);
            ldsm4(b1, b1a + l * 64);
            mma16816(acc0, A[2 * l],     b0[0], b0[1]);
            mma16816(acc0, A[2 * l + 1], b0[2], b0[3]);
            mma16816(acc1, A[2 * l],     b1[0], b1[1]);
            mma16816(acc1, A[2 * l + 1], b1[2], b1[3]);
        }
        #pragma unroll
        for (int h = 0; h < 2; ++h) {
            const int nt = 2 * ntp + h;
            const float* acc = h ? acc1 : acc0;
            float2 cl0 = c2w [4 * nt + qc];
            float2 cl1 = c2w8[4 * nt + qc];
            float p0 = acc[0] + cl0.x, p1 = acc[1] + cl0.y;
            float p2 = acc[2] + cl1.x, p3 = acc[3] + cl1.y;
            if (LAST) {
                float2 hv = h2[4 * nt + qc];
                y0 += hv.x * tanh_exact(p0) + hv.y * tanh_exact(p1);
                y1 += hv.x * tanh_exact(p2) + hv.y * tanh_exact(p3);
            } else {
                // z_next[row][col]: row = qr (+8), col = nt*8 + 2qc (+1)
                uint32_t off = (uint32_t)(nt * 8 + 2 * qc) * 2;
                sts32(zs + off,             packlh(tanh_apx(p0), tanh_apx(p1)));
                sts32(zs + 8 * LDZ_B + off, packlh(tanh_apx(p2), tanh_apx(p3)));
            }
        }
    }
}

__global__ void __launch_bounds__(THREADS, 1)
deq_mma_kernel(const float* __restrict__ x,
               const float* __restrict__ Aw,
               const float* __restrict__ Ab,
               const float* __restrict__ Bw,
               const float* __restrict__ Bb,
               const float* __restrict__ hw,
               const float* __restrict__ hb,
               float* __restrict__ out,
               int nbands)
{
    extern __shared__ char smem[];
    const int tid = threadIdx.x;

    // ---- one-time staging: B (bf16, padded rows), h, Aw, Ab+Bb ----
    for (int idx = tid; idx < 128 * 128; idx += THREADS) {
        int i = idx >> 7, j = idx & 127;
        *(__nv_bfloat16*)(smem + SM_B + i * LDB_B + j * 2) = __float2bfloat16(Bw[idx]);
    }
    if (tid < 128) {
        ((float*)(smem + SM_H))[tid]  = hw[tid];
        ((float*)(smem + SM_AB))[tid] = Ab[tid] + Bb[tid];
        ((float4*)(smem + SM_AW))[tid] = ((const float4*)Aw)[tid];
    }
    __syncthreads();

    // ---- per-thread constants ----
    const int lane = tid & 31, wid = tid >> 5;
    const int qr = lane >> 2, qc = lane & 3;
    float* cbase = (float*)(smem + SM_C + wid * CSLICE);
    const float2* c2w  = (const float2*)cbase + qr * (LDC_F / 2);
    const float2* c2w8 = c2w + 8 * (LDC_F / 2);
    const float2* h2   = (const float2*)(smem + SM_H);
    const float*  abv  = (const float*)(smem + SM_AB);
    const float4* awv  = (const float4*)(smem + SM_AW);
    const uint32_t sb  = (uint32_t)__cvta_generic_to_shared(smem);
    const uint32_t bb  = sb + SM_B + (uint32_t)(lane & 7) * LDB_B + (uint32_t)(lane >> 3) * 16;
    const uint32_t zb  = sb + SM_Z + (uint32_t)wid * ZSLICE;
    // ldmatrix A source: lanes 0-15 -> rows, lanes 16-31 -> +16B (k 8-15)
    const uint32_t za  = zb + (uint32_t)(lane & 15) * LDZ_B + (uint32_t)(lane >> 4) * 16;
    // epilogue STS target: row qr, col offset added per nt
    const uint32_t zs  = zb + (uint32_t)qr * LDZ_B;
    const float hb0 = hb[0];

    const int cr  = lane >> 1;          // c/z1 compute: this lane's row in band
    const int ci0 = (lane & 1) << 6;    // and its half of the state dim
    float* crow = cbase + cr * LDC_F;
    const uint32_t zrow = zb + (uint32_t)cr * LDZ_B;

    for (int band = blockIdx.x * NWARPS + wid; band < nbands;
         band += gridDim.x * NWARPS) {
        const int row0 = band * 16;

        // ---- c = x A^T + (A_b + B_b); z1 = tanh(c) -> Z smem ----
        __syncwarp();   // previous band's c/Z reads are done
        {
            float4 xv = ((const float4*)x)[row0 + cr];
            #pragma unroll 4
            for (int k = 0; k < 64; k += 2) {
                int i = ci0 + k;
                float4 a0 = awv[i], a1 = awv[i + 1];
                float v0 = abv[i]     + xv.x * a0.x + xv.y * a0.y + xv.z * a0.z + xv.w * a0.w;
                float v1 = abv[i + 1] + xv.x * a1.x + xv.y * a1.y + xv.z * a1.z + xv.w * a1.w;
                crow[i]     = v0;
                crow[i + 1] = v1;
                sts32(zrow + (uint32_t)i * 2, packlh(tanh_apx(v0), tanh_apx(v1)));
            }
        }
        __syncwarp();

        // ---- 3 GEMM iterations (z2, z3, z4); last fuses y = z4 . h ----
        float y0 = 0.f, y1 = 0.f;
        gemm_iter<false>(bb, za, zs, c2w, c2w8, h2, y0, y1, qc);
        __syncwarp();
        gemm_iter<false>(bb, za, zs, c2w, c2w8, h2, y0, y1, qc);
        __syncwarp();
        gemm_iter<true >(bb, za, zs, c2w, c2w8, h2, y0, y1, qc);

        // ---- reduce y across the 4 lanes sharing a row, write out ----
        y0 += __shfl_xor_sync(0xffffffffu, y0, 1);
        y0 += __shfl_xor_sync(0xffffffffu, y0, 2);
        y1 += __shfl_xor_sync(0xffffffffu, y1, 1);
        y1 += __shfl_xor_sync(0xffffffffu, y1, 2);
        if (qc == 0) {
            out[row0 + qr]     = y0 + hb0;
            out[row0 + qr + 8] = y1 + hb0;
        }
    }
}

extern "C" void kernel_launch(void* const* d_in, const int* in_sizes, int n_in,
                              void* d_out, int out_size) {
    const float* x  = (const float*)d_in[0];
    const float* Aw = (const float*)d_in[1];
    const float* Ab = (const float*)d_in[2];
    const float* Bw = (const float*)d_in[3];
    const float* Bb = (const float*)d_in[4];
    const float* hw = (const float*)d_in[5];
    const float* hb = (const float*)d_in[6];
    float* out = (float*)d_out;

    int batch  = in_sizes[0] / 4;   // x is [batch, 4]
    int nbands = batch / 16;        // 8192
    int grid   = 148;               // persistent: one CTA per SM

    cudaFuncSetAttribute(deq_mma_kernel,
                         cudaFuncAttributeMaxDynamicSharedMemorySize,
                         SM_TOTAL);
    deq_mma_kernel<<<grid, THREADS, SM_TOTAL>>>(x, Aw, Ab, Bw, Bb, hw, hb, out, nbands);
}

// round 12
// speedup vs baseline: 2.3479x; 1.2345x over previous
#include <cuda_runtime.h>
#include <cuda_bf16.h>
#include <cstdint>

// DEQ via warp-level bf16 HMMA: z <- tanh(c + z B^T), THREE tanh applications
// (z1 = tanh(c), z2, z3; measured contraction ~0.058/iter puts truncation at
// ~5e-5 abs, ~1.7e-4 rel on y, vs bf16 noise floor 1.4e-4 -> total ~3e-4).
// y = z3 . h + hb fused into the last GEMM iteration.
// R12 = R11 shape (384 thr, 3 warps/SMSP, z in per-warp SMEM between
// iterations, independent 16-row bands, persistent grid) minus one GEMM iter.

#define THREADS 384
#define NWARPS  12
#define LDB_B   272        // bytes per B row (136 bf16: conflict-free LDSM)
#define LDZ_B   272        // bytes per z row (same padding)
#define LDC_F   132        // floats per c row
#define ZSLICE  (16 * LDZ_B)        // 4352 B per warp
#define CSLICE  (16 * LDC_F * 4)    // 8448 B per warp
#define SM_B    0                   // 34816 B
#define SM_Z    34816               // 12 * 4352 = 52224 B
#define SM_C    87040               // 12 * 8448 = 101376 B
#define SM_H    188416              // 512 B
#define SM_AW   188928              // 2048 B
#define SM_AB   190976              // 512 B
#define SM_TOTAL 191488

__device__ __forceinline__ float tanh_exact(float v) {
    float e = __expf(2.0f * v);
    return 1.0f - __fdividef(2.0f, e + 1.0f);
}
__device__ __forceinline__ float tanh_apx(float v) {
    float r; asm("tanh.approx.f32 %0, %1;" : "=f"(r) : "f"(v)); return r;
}
// pack {lo, hi} floats into bf16x2 (lo -> low 16 bits)
__device__ __forceinline__ uint32_t packlh(float lo, float hi) {
    uint32_t r;
    asm("cvt.rn.satfinite.bf16x2.f32 %0, %1, %2;" : "=r"(r) : "f"(hi), "f"(lo));
    return r;
}
__device__ __forceinline__ void mma16816(float* d, const uint32_t* a,
                                         uint32_t b0, uint32_t b1) {
    asm volatile(
        "mma.sync.aligned.m16n8k16.row.col.f32.bf16.bf16.f32 "
        "{%0,%1,%2,%3}, {%4,%5,%6,%7}, {%8,%9}, {%0,%1,%2,%3};"
        : "+f"(d[0]), "+f"(d[1]), "+f"(d[2]), "+f"(d[3])
        : "r"(a[0]), "r"(a[1]), "r"(a[2]), "r"(a[3]), "r"(b0), "r"(b1));
}
__device__ __forceinline__ void ldsm4(uint32_t* r, uint32_t addr) {
    asm volatile("ldmatrix.sync.aligned.m8n8.x4.shared.b16 {%0,%1,%2,%3}, [%4];"
                 : "=r"(r[0]), "=r"(r[1]), "=r"(r[2]), "=r"(r[3]) : "r"(addr));
}
__device__ __forceinline__ void sts32(uint32_t addr, uint32_t v) {
    asm volatile("st.shared.b32 [%0], %1;" :: "r"(addr), "r"(v) : "memory");
}

// One GEMM iteration: out = z_cur * B^T (A fragments loaded from Z smem);
// z_next = tanh(c + out) -> STS back to Z smem (or y-reduce on LAST).
template<bool LAST>
__device__ __forceinline__ void gemm_iter(
    uint32_t bb, uint32_t za, uint32_t zs,
    const float2* c2w, const float2* c2w8, const float2* h2,
    float& y0, float& y1, int qc)
{
    // load A fragments for this iteration (z_cur)
    uint32_t A[8][4];
    #pragma unroll
    for (int kt = 0; kt < 8; ++kt)
        ldsm4(A[kt], za + kt * 32);

    #pragma unroll
    for (int ntp = 0; ntp < 8; ++ntp) {
        const uint32_t b0a = bb + (uint32_t)(2 * ntp)     * (8 * LDB_B);
        const uint32_t b1a = bb + (uint32_t)(2 * ntp + 1) * (8 * LDB_B);
        float acc0[4] = {0.f, 0.f, 0.f, 0.f};
        float acc1[4] = {0.f, 0.f, 0.f, 0.f};
        #pragma unroll
        for (int l = 0; l < 4; ++l) {
            uint32_t b0[4], b1[4];
            ldsm4(b0, b0a + l * 64);
            ldsm4(b1, b1a + l * 64);
            mma16816(acc0, A[2 * l],     b0[0], b0[1]);
            mma16816(acc0, A[2 * l + 1], b0[2], b0[3]);
            mma16816(acc1, A[2 * l],     b1[0], b1[1]);
            mma16816(acc1, A[2 * l + 1], b1[2], b1[3]);
        }
        #pragma unroll
        for (int h = 0; h < 2; ++h) {
            const int nt = 2 * ntp + h;
            const float* acc = h ? acc1 : acc0;
            float2 cl0 = c2w [4 * nt + qc];
            float2 cl1 = c2w8[4 * nt + qc];
            float p0 = acc[0] + cl0.x, p1 = acc[1] + cl0.y;
            float p2 = acc[2] + cl1.x, p3 = acc[3] + cl1.y;
            if (LAST) {
                float2 hv = h2[4 * nt + qc];
                y0 += hv.x * tanh_exact(p0) + hv.y * tanh_exact(p1);
                y1 += hv.x * tanh_exact(p2) + hv.y * tanh_exact(p3);
            } else {
                // z_next[row][col]: row = qr (+8), col = nt*8 + 2qc (+1)
                uint32_t off = (uint32_t)(nt * 8 + 2 * qc) * 2;
                sts32(zs + off,             packlh(tanh_apx(p0), tanh_apx(p1)));
                sts32(zs + 8 * LDZ_B + off, packlh(tanh_apx(p2), tanh_apx(p3)));
            }
        }
    }
}

__global__ void __launch_bounds__(THREADS, 1)
deq_mma_kernel(const float* __restrict__ x,
               const float* __restrict__ Aw,
               const float* __restrict__ Ab,
               const float* __restrict__ Bw,
               const float* __restrict__ Bb,
               const float* __restrict__ hw,
               const float* __restrict__ hb,
               float* __restrict__ out,
               int nbands)
{
    extern __shared__ char smem[];
    const int tid = threadIdx.x;

    // ---- one-time staging: B (bf16, padded rows), h, Aw, Ab+Bb ----
    for (int idx = tid; idx < 128 * 128; idx += THREADS) {
        int i = idx >> 7, j = idx & 127;
        *(__nv_bfloat16*)(smem + SM_B + i * LDB_B + j * 2) = __float2bfloat16(Bw[idx]);
    }
    if (tid < 128) {
        ((float*)(smem + SM_H))[tid]  = hw[tid];
        ((float*)(smem + SM_AB))[tid] = Ab[tid] + Bb[tid];
        ((float4*)(smem + SM_AW))[tid] = ((const float4*)Aw)[tid];
    }
    __syncthreads();

    // ---- per-thread constants ----
    const int lane = tid & 31, wid = tid >> 5;
    const int qr = lane >> 2, qc = lane & 3;
    float* cbase = (float*)(smem + SM_C + wid * CSLICE);
    const float2* c2w  = (const float2*)cbase + qr * (LDC_F / 2);
    const float2* c2w8 = c2w + 8 * (LDC_F / 2);
    const float2* h2   = (const float2*)(smem + SM_H);
    const float*  abv  = (const float*)(smem + SM_AB);
    const float4* awv  = (const float4*)(smem + SM_AW);
    const uint32_t sb  = (uint32_t)__cvta_generic_to_shared(smem);
    const uint32_t bb  = sb + SM_B + (uint32_t)(lane & 7) * LDB_B + (uint32_t)(lane >> 3) * 16;
    const uint32_t zb  = sb + SM_Z + (uint32_t)wid * ZSLICE;
    // ldmatrix A source: lanes 0-15 -> rows, lanes 16-31 -> +16B (k 8-15)
    const uint32_t za  = zb + (uint32_t)(lane & 15) * LDZ_B + (uint32_t)(lane >> 4) * 16;
    // epilogue STS target: row qr, col offset added per nt
    const uint32_t zs  = zb + (uint32_t)qr * LDZ_B;
    const float hb0 = hb[0];

    const int cr  = lane >> 1;          // c/z1 compute: this lane's row in band
    const int ci0 = (lane & 1) << 6;    // and its half of the state dim
    float* crow = cbase + cr * LDC_F;
    const uint32_t zrow = zb + (uint32_t)cr * LDZ_B;

    for (int band = blockIdx.x * NWARPS + wid; band < nbands;
         band += gridDim.x * NWARPS) {
        const int row0 = band * 16;

        // ---- c = x A^T + (A_b + B_b); z1 = tanh(c) -> Z smem ----
        __syncwarp();   // previous band's c/Z reads are done
        {
            float4 xv = ((const float4*)x)[row0 + cr];
            #pragma unroll 4
            for (int k = 0; k < 64; k += 2) {
                int i = ci0 + k;
                float4 a0 = awv[i], a1 = awv[i + 1];
                float v0 = abv[i]     + xv.x * a0.x + xv.y * a0.y + xv.z * a0.z + xv.w * a0.w;
                float v1 = abv[i + 1] + xv.x * a1.x + xv.y * a1.y + xv.z * a1.z + xv.w * a1.w;
                crow[i]     = v0;
                crow[i + 1] = v1;
                sts32(zrow + (uint32_t)i * 2, packlh(tanh_apx(v0), tanh_apx(v1)));
            }
        }
        __syncwarp();

        // ---- 2 GEMM iterations (z2, z3); last fuses y = z3 . h ----
        float y0 = 0.f, y1 = 0.f;
        gemm_iter<false>(bb, za, zs, c2w, c2w8, h2, y0, y1, qc);
        __syncwarp();
        gemm_iter<true >(bb, za, zs, c2w, c2w8, h2, y0, y1, qc);

        // ---- reduce y across the 4 lanes sharing a row, write out ----
        y0 += __shfl_xor_sync(0xffffffffu, y0, 1);
        y0 += __shfl_xor_sync(0xffffffffu, y0, 2);
        y1 += __shfl_xor_sync(0xffffffffu, y1, 1);
        y1 += __shfl_xor_sync(0xffffffffu, y1, 2);
        if (qc == 0) {
            out[row0 + qr]     = y0 + hb0;
            out[row0 + qr + 8] = y1 + hb0;
        }
    }
}

extern "C" void kernel_launch(void* const* d_in, const int* in_sizes, int n_in,
                              void* d_out, int out_size) {
    const float* x  = (const float*)d_in[0];
    const float* Aw = (const float*)d_in[1];
    const float* Ab = (const float*)d_in[2];
    const float* Bw = (const float*)d_in[3];
    const float* Bb = (const float*)d_in[4];
    const float* hw = (const float*)d_in[5];
    const float* hb = (const float*)d_in[6];
    float* out = (float*)d_out;

    int batch  = in_sizes[0] / 4;   // x is [batch, 4]
    int nbands = batch / 16;        // 8192
    int grid   = 148;               // persistent: one CTA per SM

    cudaFuncSetAttribute(deq_mma_kernel,
                         cudaFuncAttributeMaxDynamicSharedMemorySize,
                         SM_TOTAL);
    deq_mma_kernel<<<grid, THREADS, SM_TOTAL>>>(x, Aw, Ab, Bw, Bb, hw, hb, out, nbands);
}

// round 13
// speedup vs baseline: 2.7745x; 1.1817x over previous
#include <cuda_runtime.h>
#include <cuda_bf16.h>
#include <cstdint>

// DEQ via warp-level bf16 HMMA, c folded into the GEMM:
//   z~ = [z(128) | x_hi(4) | x_lo(4) | 1 | 1 | 0...]  (K = 144, 9 k-tiles)
//   W~ = [B      | Aw      | Aw      | bias_hi | bias_lo | 0]
// so pre-act = z.B^T + x.Aw^T + bias exactly (hi/lo splits keep bf16 error
// ~1e-6 on the x and bias paths). 3 tanh applications: iter0 (kt8 only, z=0)
// gives z1 = tanh(c); iter1 -> z2; iter2 -> z3 fused with y = z3.h + hb.
// R13: 512 threads (16 warps, 4/SMSP, 128-reg cap), z in per-warp SMEM,
// independent 16-row bands, __syncwarp only, persistent grid. No C array.

#define THREADS 512
#define NWARPS  16
#define LDW     304        // bytes per W~/Z row (144 bf16 = 288 B + 16 pad)
#define ZSLICE  (16 * LDW) // 4864 B per warp
#define SM_W    0          // 128 * 304 = 38912 B
#define SM_Z    38912      // 16 * 4864 = 77824 B
#define SM_H    116736     // 512 B
#define SM_TOTAL 117248

__device__ __forceinline__ float tanh_exact(float v) {
    float e = __expf(2.0f * v);
    return 1.0f - __fdividef(2.0f, e + 1.0f);
}
__device__ __forceinline__ float tanh_apx(float v) {
    float r; asm("tanh.approx.f32 %0, %1;" : "=f"(r) : "f"(v)); return r;
}
// pack {lo, hi} floats into bf16x2 (lo -> low 16 bits = lower column)
__device__ __forceinline__ uint32_t packlh(float lo, float hi) {
    uint32_t r;
    asm("cvt.rn.satfinite.bf16x2.f32 %0, %1, %2;" : "=r"(r) : "f"(hi), "f"(lo));
    return r;
}
__device__ __forceinline__ void mma16816(float* d, const uint32_t* a,
                                         uint32_t b0, uint32_t b1) {
    asm volatile(
        "mma.sync.aligned.m16n8k16.row.col.f32.bf16.bf16.f32 "
        "{%0,%1,%2,%3}, {%4,%5,%6,%7}, {%8,%9}, {%0,%1,%2,%3};"
        : "+f"(d[0]), "+f"(d[1]), "+f"(d[2]), "+f"(d[3])
        : "r"(a[0]), "r"(a[1]), "r"(a[2]), "r"(a[3]), "r"(b0), "r"(b1));
}
__device__ __forceinline__ void ldsm4(uint32_t* r, uint32_t addr) {
    asm volatile("ldmatrix.sync.aligned.m8n8.x4.shared.b16 {%0,%1,%2,%3}, [%4];"
                 : "=r"(r[0]), "=r"(r[1]), "=r"(r[2]), "=r"(r[3]) : "r"(addr));
}
__device__ __forceinline__ void ldsm2(uint32_t* r, uint32_t addr) {
    asm volatile("ldmatrix.sync.aligned.m8n8.x2.shared.b16 {%0,%1}, [%2];"
                 : "=r"(r[0]), "=r"(r[1]) : "r"(addr));
}
__device__ __forceinline__ void sts32(uint32_t addr, uint32_t v) {
    asm volatile("st.shared.b32 [%0], %1;" :: "r"(addr), "r"(v) : "memory");
}
__device__ __forceinline__ void sts128(uint32_t addr, uint32_t a, uint32_t b,
                                       uint32_t c, uint32_t d) {
    asm volatile("st.shared.v4.b32 [%0], {%1,%2,%3,%4};"
                 :: "r"(addr), "r"(a), "r"(b), "r"(c), "r"(d) : "memory");
}

// One GEMM iteration over the extended K (9 k-tiles).
// FIRST: z=0, only kt8 (the c columns) contributes.
// LAST:  fuse y = z.h instead of storing z_next.
template<bool FIRST, bool LAST>
__device__ __forceinline__ void gemm_iter(
    uint32_t bb, uint32_t za, uint32_t zs, const float2* h2,
    float& y0, float& y1, int qc)
{
    uint32_t A[9][4];
    if (!FIRST) {
        #pragma unroll
        for (int kt = 0; kt < 8; ++kt) ldsm4(A[kt], za + kt * 32);
    }
    ldsm4(A[8], za + 256);   // x/ones columns (bytes 256-287)

    #pragma unroll
    for (int ntp = 0; ntp < 8; ++ntp) {
        const uint32_t b0a = bb + (uint32_t)(2 * ntp)     * (8 * LDW);
        const uint32_t b1a = bb + (uint32_t)(2 * ntp + 1) * (8 * LDW);
        float acc0[4] = {0.f, 0.f, 0.f, 0.f};
        float acc1[4] = {0.f, 0.f, 0.f, 0.f};
        if (!FIRST) {
            #pragma unroll
            for (int l = 0; l < 4; ++l) {
                uint32_t b0[4], b1[4];
                ldsm4(b0, b0a + l * 64);
                ldsm4(b1, b1a + l * 64);
                mma16816(acc0, A[2 * l],     b0[0], b0[1]);
                mma16816(acc0, A[2 * l + 1], b0[2], b0[3]);
                mma16816(acc1, A[2 * l],     b1[0], b1[1]);
                mma16816(acc1, A[2 * l + 1], b1[2], b1[3]);
            }
        }
        {   // kt8: c contribution (Aw-hi/lo + bias-hi/lo columns)
            uint32_t c0[2], c1[2];
            ldsm2(c0, b0a + 256);
            ldsm2(c1, b1a + 256);
            mma16816(acc0, A[8], c0[0], c0[1]);
            mma16816(acc1, A[8], c1[0], c1[1]);
        }
        #pragma unroll
        for (int h = 0; h < 2; ++h) {
            const int nt = 2 * ntp + h;
            const float* acc = h ? acc1 : acc0;
            if (LAST) {
                float2 hv = h2[4 * nt + qc];
                y0 += hv.x * tanh_exact(acc[0]) + hv.y * tanh_exact(acc[1]);
                y1 += hv.x * tanh_exact(acc[2]) + hv.y * tanh_exact(acc[3]);
            } else {
                uint32_t off = (uint32_t)(nt * 8 + 2 * qc) * 2;
                sts32(zs + off,           packlh(tanh_apx(acc[0]), tanh_apx(acc[1])));
                sts32(zs + 8 * LDW + off, packlh(tanh_apx(acc[2]), tanh_apx(acc[3])));
            }
        }
    }
}

__global__ void __launch_bounds__(THREADS, 1)
deq_mma_kernel(const float* __restrict__ x,
               const float* __restrict__ Aw,
               const float* __restrict__ Ab,
               const float* __restrict__ Bw,
               const float* __restrict__ Bb,
               const float* __restrict__ hw,
               const float* __restrict__ hb,
               float* __restrict__ out,
               int nbands)
{
    extern __shared__ char smem[];
    const int tid = threadIdx.x;

    // ---- one-time staging: W~ (bf16, padded rows) and h ----
    for (int idx = tid; idx < 128 * 144; idx += THREADS) {
        int n = idx / 144, k = idx % 144;
        float v;
        if (k < 128)      v = Bw[n * 128 + k];
        else if (k < 136) v = Aw[n * 4 + ((k - 128) & 3)];
        else if (k == 136) {
            float b = Ab[n] + Bb[n];
            v = __bfloat162float(__float2bfloat16(b));          // bias_hi
        } else if (k == 137) {
            float b = Ab[n] + Bb[n];
            v = b - __bfloat162float(__float2bfloat16(b));      // bias_lo
        } else v = 0.0f;
        *(__nv_bfloat16*)(smem + SM_W + n * LDW + k * 2) = __float2bfloat16(v);
    }
    if (tid < 128) ((float*)(smem + SM_H))[tid] = hw[tid];
    __syncthreads();

    // ---- per-thread constants ----
    const int lane = tid & 31, wid = tid >> 5;
    const int qr = lane >> 2, qc = lane & 3;
    const float2* h2  = (const float2*)(smem + SM_H);
    const uint32_t sb = (uint32_t)__cvta_generic_to_shared(smem);
    const uint32_t bb = sb + SM_W + (uint32_t)(lane & 7) * LDW + (uint32_t)(lane >> 3) * 16;
    const uint32_t zb = sb + SM_Z + (uint32_t)wid * ZSLICE;
    const uint32_t za = zb + (uint32_t)(lane & 15) * LDW + (uint32_t)(lane >> 4) * 16;
    const uint32_t zs = zb + (uint32_t)qr * LDW;
    const float hb0 = hb[0];

    const int cr = lane >> 1;                         // prologue: lane pair per row
    const uint32_t zrow = zb + (uint32_t)cr * LDW;
    const uint32_t ONES = packlh(1.0f, 1.0f);

    for (int band = blockIdx.x * NWARPS + wid; band < nbands;
         band += gridDim.x * NWARPS) {
        const int row0 = band * 16;

        // ---- prologue: write x_hi/x_lo/ones columns (bytes 256-287) ----
        __syncwarp();   // previous band's ldsm reads of Z are done
        {
            float4 xv = ((const float4*)x)[row0 + cr];
            if ((lane & 1) == 0) {
                float hx = __bfloat162float(__float2bfloat16(xv.x));
                float hy = __bfloat162float(__float2bfloat16(xv.y));
                float hz = __bfloat162float(__float2bfloat16(xv.z));
                float hw_ = __bfloat162float(__float2bfloat16(xv.w));
                sts128(zrow + 256,
                       packlh(xv.x, xv.y), packlh(xv.z, xv.w),
                       packlh(xv.x - hx, xv.y - hy), packlh(xv.z - hz, xv.w - hw_));
            } else {
                sts128(zrow + 272, ONES, 0u, 0u, 0u);
            }
        }
        __syncwarp();

        // ---- 3 applications: z1 (kt8 only), z2, z3 + y ----
        float y0 = 0.f, y1 = 0.f;
        gemm_iter<true,  false>(bb, za, zs, h2, y0, y1, qc);
        __syncwarp();
        gemm_iter<false, false>(bb, za, zs, h2, y0, y1, qc);
        __syncwarp();
        gemm_iter<false, true >(bb, za, zs, h2, y0, y1, qc);

        // ---- reduce y across the 4 lanes sharing a row, write out ----
        y0 += __shfl_xor_sync(0xffffffffu, y0, 1);
        y0 += __shfl_xor_sync(0xffffffffu, y0, 2);
        y1 += __shfl_xor_sync(0xffffffffu, y1, 1);
        y1 += __shfl_xor_sync(0xffffffffu, y1, 2);
        if (qc == 0) {
            out[row0 + qr]     = y0 + hb0;
            out[row0 + qr + 8] = y1 + hb0;
        }
    }
}

extern "C" void kernel_launch(void* const* d_in, const int* in_sizes, int n_in,
                              void* d_out, int out_size) {
    const float* x  = (const float*)d_in[0];
    const float* Aw = (const float*)d_in[1];
    const float* Ab = (const float*)d_in[2];
    const float* Bw = (const float*)d_in[3];
    const float* Bb = (const float*)d_in[4];
    const float* hw = (const float*)d_in[5];
    const float* hb = (const float*)d_in[6];
    float* out = (float*)d_out;

    int batch  = in_sizes[0] / 4;   // x is [batch, 4]
    int nbands = batch / 16;        // 8192
    int grid   = 148;               // persistent: one CTA per SM

    cudaFuncSetAttribute(deq_mma_kernel,
                         cudaFuncAttributeMaxDynamicSharedMemorySize,
                         SM_TOTAL);
    deq_mma_kernel<<<grid, THREADS, SM_TOTAL>>>(x, Aw, Ab, Bw, Bb, hw, hb, out, nbands);
}